// round 2
// baseline (speedup 1.0000x reference)
#include <cuda_runtime.h>
#include <cstdint>

#define N_NODES 50000
#define E_EDGES 800000
#define DIM 128
#define ODIM 128
#define M_CNT (2 * N_NODES)           // 100000 (rel,row) counters
#define SCAN_T 1024
#define CHUNK  98                     // ceil(M_CNT / SCAN_T)

// Projected features, interleaved: g_x[n][0..127]=x1[n], [128..255]=x2[n]
__device__ float  g_x[(size_t)N_NODES * 256];
// Row-sorted edges: (col bits, val) packed as float2
__device__ float2 g_edges[(size_t)2 * E_EDGES];
__device__ int    g_counts[M_CNT];
__device__ int    g_start[M_CNT + 1];
__device__ int    g_cursor[M_CNT];

// ---------------------------------------------------------------------------
// Dense projection GEMM (unchanged from R1): 64x128 tile, 256 thr, 8x4/thread
// ---------------------------------------------------------------------------
#define GEMM_SMEM_BYTES (128 * 72 * 4 + 128 * 32 * 16)   // 100 KB

__global__ void __launch_bounds__(256) gemm_kernel(
    const float* __restrict__ A,
    const float* __restrict__ W1,
    const float* __restrict__ W2)
{
    extern __shared__ float smem[];
    float*  As = smem;                        // [128][72] k-major, padded
    float4* Bs = (float4*)(smem + 128 * 72);  // [128][32] float4

    const float* W = (blockIdx.y == 0) ? W1 : W2;
    const int row0 = blockIdx.x * 64;
    const int tid  = threadIdx.x;

    const float4* W4 = (const float4*)W;
    #pragma unroll
    for (int i = 0; i < 16; i++) {
        int idx = tid + i * 256;
        Bs[idx] = W4[idx];
    }

    const float4* A4 = (const float4*)A;
    #pragma unroll
    for (int i = 0; i < 8; i++) {
        int idx = tid + i * 256;
        int r   = idx >> 5;
        int c4  = idx & 31;
        float4 v = make_float4(0.f, 0.f, 0.f, 0.f);
        int grow = row0 + r;
        if (grow < N_NODES) v = A4[(size_t)grow * 32 + c4];
        int k = c4 * 4;
        As[(k + 0) * 72 + r] = v.x;
        As[(k + 1) * 72 + r] = v.y;
        As[(k + 2) * 72 + r] = v.z;
        As[(k + 3) * 72 + r] = v.w;
    }
    __syncthreads();

    const int n_idx = tid & 31;
    const int m_idx = tid >> 5;

    float4 acc[8];
    #pragma unroll
    for (int r = 0; r < 8; r++) acc[r] = make_float4(0.f, 0.f, 0.f, 0.f);

    const float4* As4 = (const float4*)As;

    #pragma unroll 4
    for (int k = 0; k < 128; k++) {
        float4 b  = Bs[k * 32 + n_idx];
        float4 a0 = As4[k * 18 + m_idx * 2];
        float4 a1 = As4[k * 18 + m_idx * 2 + 1];
        float a_arr[8] = {a0.x, a0.y, a0.z, a0.w, a1.x, a1.y, a1.z, a1.w};
        #pragma unroll
        for (int r = 0; r < 8; r++) {
            acc[r].x += a_arr[r] * b.x;
            acc[r].y += a_arr[r] * b.y;
            acc[r].z += a_arr[r] * b.z;
            acc[r].w += a_arr[r] * b.w;
        }
    }

    float4* X4 = (float4*)g_x;
    const int col4 = blockIdx.y * 32 + n_idx;
    #pragma unroll
    for (int r = 0; r < 8; r++) {
        int grow = row0 + m_idx * 8 + r;
        if (grow < N_NODES) X4[(size_t)grow * 64 + col4] = acc[r];
    }
}

// ---------------------------------------------------------------------------
// Counting sort by (rel, row)
// ---------------------------------------------------------------------------
__global__ void zero_counts_kernel() {
    int i = blockIdx.x * blockDim.x + threadIdx.x;
    if (i < M_CNT) g_counts[i] = 0;
}

__global__ void hist_kernel(const int* __restrict__ r1, const int* __restrict__ r2) {
    int t = blockIdx.x * blockDim.x + threadIdx.x;
    if (t >= 2 * E_EDGES) return;
    int rel = (t >= E_EDGES);
    int e   = t - rel * E_EDGES;
    int row = rel ? __ldg(r2 + e) : __ldg(r1 + e);
    atomicAdd(&g_counts[rel * N_NODES + row], 1);
}

// Single-block exclusive scan over 100k counters; emits g_start and g_cursor.
__global__ void __launch_bounds__(SCAN_T) scan_kernel() {
    __shared__ int s[SCAN_T];
    int t = threadIdx.x;
    int base = t * CHUNK;

    int sum = 0;
    #pragma unroll 7
    for (int j = 0; j < CHUNK; j++) {
        int i = base + j;
        if (i < M_CNT) sum += g_counts[i];
    }
    s[t] = sum;
    __syncthreads();

    // Hillis-Steele inclusive scan
    for (int off = 1; off < SCAN_T; off <<= 1) {
        int v = 0;
        if (t >= off) v = s[t - off];
        __syncthreads();
        if (t >= off) s[t] += v;
        __syncthreads();
    }

    int run = s[t] - sum;   // exclusive base for this chunk
    for (int j = 0; j < CHUNK; j++) {
        int i = base + j;
        if (i < M_CNT) {
            g_start[i]  = run;
            g_cursor[i] = run;
            run += g_counts[i];
        }
    }
    if (t == SCAN_T - 1) g_start[M_CNT] = s[SCAN_T - 1];
}

__global__ void reorder_kernel(
    const int* __restrict__ r1, const int* __restrict__ c1, const float* __restrict__ v1,
    const int* __restrict__ r2, const int* __restrict__ c2, const float* __restrict__ v2)
{
    int t = blockIdx.x * blockDim.x + threadIdx.x;
    if (t >= 2 * E_EDGES) return;
    int rel = (t >= E_EDGES);
    int e   = t - rel * E_EDGES;
    int row, col; float val;
    if (rel == 0) { row = __ldg(r1 + e); col = __ldg(c1 + e); val = __ldg(v1 + e); }
    else          { row = __ldg(r2 + e); col = __ldg(c2 + e); val = __ldg(v2 + e); }
    int pos = atomicAdd(&g_cursor[rel * N_NODES + row], 1);
    g_edges[pos] = make_float2(__int_as_float(col), val);
}

// ---------------------------------------------------------------------------
// Row gather: one block per output row, 4 warps edge-parallel, fused ReLU.
// ---------------------------------------------------------------------------
__global__ void __launch_bounds__(128) gather_kernel(float* __restrict__ out)
{
    const int row  = blockIdx.x;
    const int lane = threadIdx.x & 31;
    const int ew   = threadIdx.x >> 5;   // warp id 0..3

    float4 acc = make_float4(0.f, 0.f, 0.f, 0.f);
    const float4* X4 = (const float4*)g_x;

    #pragma unroll
    for (int rel = 0; rel < 2; rel++) {
        const int i  = rel * N_NODES + row;
        const int s  = g_start[i];
        const int en = g_start[i + 1];
        for (int e = s + ew; e < en; e += 4) {
            float2 p  = __ldg(&g_edges[e]);
            int   col = __float_as_int(p.x);
            float val = p.y;
            float4 x  = __ldg(X4 + (size_t)col * 64 + rel * 32 + lane);
            acc.x += val * x.x;
            acc.y += val * x.y;
            acc.z += val * x.z;
            acc.w += val * x.w;
        }
    }

    __shared__ float4 sacc[4][32];
    sacc[ew][lane] = acc;
    __syncthreads();

    if (ew == 0) {
        float4 a = sacc[0][lane];
        #pragma unroll
        for (int w = 1; w < 4; w++) {
            float4 b = sacc[w][lane];
            a.x += b.x; a.y += b.y; a.z += b.z; a.w += b.w;
        }
        a.x = fmaxf(a.x, 0.f);
        a.y = fmaxf(a.y, 0.f);
        a.z = fmaxf(a.z, 0.f);
        a.w = fmaxf(a.w, 0.f);
        ((float4*)out)[(size_t)row * 32 + lane] = a;
    }
}

// ---------------------------------------------------------------------------
extern "C" void kernel_launch(void* const* d_in, const int* in_sizes, int n_in,
                              void* d_out, int out_size)
{
    const float* inputs = (const float*)d_in[0];
    const int*   r1     = (const int*)  d_in[1];
    const int*   c1     = (const int*)  d_in[2];
    const float* v1     = (const float*)d_in[3];
    const int*   r2     = (const int*)  d_in[4];
    const int*   c2     = (const int*)  d_in[5];
    const float* v2     = (const float*)d_in[6];
    const float* W1     = (const float*)d_in[7];
    const float* W2     = (const float*)d_in[8];
    float*       out    = (float*)d_out;

    cudaFuncSetAttribute(gemm_kernel,
                         cudaFuncAttributeMaxDynamicSharedMemorySize,
                         GEMM_SMEM_BYTES);

    // Sort chain (independent of GEMM)
    zero_counts_kernel<<<(M_CNT + 255) / 256, 256>>>();
    hist_kernel<<<(2 * E_EDGES + 255) / 256, 256>>>(r1, r2);
    scan_kernel<<<1, SCAN_T>>>();
    reorder_kernel<<<(2 * E_EDGES + 255) / 256, 256>>>(r1, c1, v1, r2, c2, v2);

    // Dense projection
    {
        dim3 grid((N_NODES + 63) / 64, 2);
        gemm_kernel<<<grid, 256, GEMM_SMEM_BYTES>>>(inputs, W1, W2);
    }

    // Row gather + fused ReLU (writes every output row; no zero/relu pass)
    gather_kernel<<<N_NODES, 128>>>(out);
}

// round 3
// speedup vs baseline: 1.2183x; 1.2183x over previous
#include <cuda_runtime.h>
#include <cuda_fp16.h>
#include <cstdint>

#define N_NODES 50000
#define E_EDGES 800000
#define ODIM 128

// Projected features in fp16, interleaved per node as half2:
// cols [0,64) = relation 1 (128 halves), cols [64,128) = relation 2
__device__ __half2 g_x2[(size_t)N_NODES * 128];

// ---------------------------------------------------------------------------
// Tensor-core GEMM (tf32 x3 split): g_x2[n][rel] = inputs[n] @ W_rel
// BM=128, BN=128 (one relation per blockIdx.y), K=128 in one smem stage.
// 8 warps: warp_m = wid&3 (32 rows), warp_n = wid>>2 (64 cols).
// Per warp: 2 m-tiles x 8 n-tiles of m16n8k8, 16 k-steps, 3 split products.
// ---------------------------------------------------------------------------
#define STRIDE 132
#define GEMM_SMEM_BYTES (2 * 128 * STRIDE * 4)   // As + Bs = 132 KB

__device__ __forceinline__ void cvt_split(float v, uint32_t& hi, uint32_t& lo) {
    asm("cvt.rna.tf32.f32 %0, %1;" : "=r"(hi) : "f"(v));
    float r = v - __uint_as_float(hi);
    asm("cvt.rna.tf32.f32 %0, %1;" : "=r"(lo) : "f"(r));
}

__device__ __forceinline__ void mma8(float* c, const uint32_t* a,
                                     uint32_t b0, uint32_t b1) {
    asm volatile(
        "mma.sync.aligned.m16n8k8.row.col.f32.tf32.tf32.f32 "
        "{%0,%1,%2,%3}, {%4,%5,%6,%7}, {%8,%9}, {%0,%1,%2,%3};"
        : "+f"(c[0]), "+f"(c[1]), "+f"(c[2]), "+f"(c[3])
        : "r"(a[0]), "r"(a[1]), "r"(a[2]), "r"(a[3]), "r"(b0), "r"(b1));
}

__global__ void __launch_bounds__(256) gemm_tc_kernel(
    const float* __restrict__ A,
    const float* __restrict__ W1,
    const float* __restrict__ W2)
{
    extern __shared__ float smem[];
    float* As = smem;                    // [m][k] stride 132
    float* Bs = smem + 128 * STRIDE;     // [n][k] stride 132

    const float* W = (blockIdx.y == 0) ? W1 : W2;
    const int row0 = blockIdx.x * 128;
    const int tid  = threadIdx.x;

    // Stage A tile (128x128 fp32), zero-padded past N_NODES.
    const float4* A4 = (const float4*)A;
    #pragma unroll
    for (int i = 0; i < 16; i++) {
        int idx = tid + i * 256;          // 0..4095 float4
        int m   = idx >> 5;
        int c4  = idx & 31;
        float4 v = make_float4(0.f, 0.f, 0.f, 0.f);
        if (row0 + m < N_NODES) v = A4[(size_t)(row0 + m) * 32 + c4];
        float* dst = As + m * STRIDE + c4 * 4;
        dst[0] = v.x; dst[1] = v.y; dst[2] = v.z; dst[3] = v.w;
    }
    // Stage B transposed: W[k][n] row-major -> Bs[n][k].
    const float4* W4 = (const float4*)W;
    #pragma unroll
    for (int i = 0; i < 16; i++) {
        int idx = tid + i * 256;          // 0..4095 float4
        int k   = idx >> 5;
        int n4  = idx & 31;
        float4 v = W4[idx];
        Bs[(n4 * 4 + 0) * STRIDE + k] = v.x;
        Bs[(n4 * 4 + 1) * STRIDE + k] = v.y;
        Bs[(n4 * 4 + 2) * STRIDE + k] = v.z;
        Bs[(n4 * 4 + 3) * STRIDE + k] = v.w;
    }
    __syncthreads();

    const int wid  = tid >> 5;
    const int lane = tid & 31;
    const int wm   = wid & 3;      // 0..3  -> rows wm*32
    const int wn   = wid >> 2;     // 0..1  -> cols wn*64
    const int g    = lane >> 2;    // group 0..7
    const int t    = lane & 3;     // tid-in-group 0..3

    float c[2][8][4];
    #pragma unroll
    for (int mt = 0; mt < 2; mt++)
        #pragma unroll
        for (int nt = 0; nt < 8; nt++)
            #pragma unroll
            for (int j = 0; j < 4; j++) c[mt][nt][j] = 0.f;

    #pragma unroll 1
    for (int ks = 0; ks < 16; ks++) {
        const int k0 = ks * 8;
        uint32_t ah[2][4], al[2][4];
        #pragma unroll
        for (int mt = 0; mt < 2; mt++) {
            const int r0 = wm * 32 + mt * 16;
            float v0 = As[(r0 + g)     * STRIDE + k0 + t];
            float v1 = As[(r0 + g + 8) * STRIDE + k0 + t];
            float v2 = As[(r0 + g)     * STRIDE + k0 + t + 4];
            float v3 = As[(r0 + g + 8) * STRIDE + k0 + t + 4];
            cvt_split(v0, ah[mt][0], al[mt][0]);
            cvt_split(v1, ah[mt][1], al[mt][1]);
            cvt_split(v2, ah[mt][2], al[mt][2]);
            cvt_split(v3, ah[mt][3], al[mt][3]);
        }
        #pragma unroll
        for (int nt = 0; nt < 8; nt++) {
            const int n = wn * 64 + nt * 8 + g;
            float w0 = Bs[n * STRIDE + k0 + t];
            float w1 = Bs[n * STRIDE + k0 + t + 4];
            uint32_t bh0, bl0, bh1, bl1;
            cvt_split(w0, bh0, bl0);
            cvt_split(w1, bh1, bl1);
            #pragma unroll
            for (int mt = 0; mt < 2; mt++) {
                mma8(c[mt][nt], ah[mt], bh0, bh1);   // hi*hi
                mma8(c[mt][nt], al[mt], bh0, bh1);   // lo*hi
                mma8(c[mt][nt], ah[mt], bl0, bl1);   // hi*lo
            }
        }
    }

    // Epilogue: pack adjacent col pairs (2t, 2t+1) into half2 and store.
    #pragma unroll
    for (int mt = 0; mt < 2; mt++) {
        #pragma unroll
        for (int nt = 0; nt < 8; nt++) {
            const int row_a = row0 + wm * 32 + mt * 16 + g;
            const int row_b = row_a + 8;
            const int h2col = blockIdx.y * 64 + wn * 32 + nt * 4 + t;
            if (row_a < N_NODES)
                g_x2[(size_t)row_a * 128 + h2col] =
                    __floats2half2_rn(c[mt][nt][0], c[mt][nt][1]);
            if (row_b < N_NODES)
                g_x2[(size_t)row_b * 128 + h2col] =
                    __floats2half2_rn(c[mt][nt][2], c[mt][nt][3]);
        }
    }
}

// ---------------------------------------------------------------------------
// Scatter: one warp per (edge, rel). Lane l covers features 4l..4l+3:
// one 8B fp16 load (2x half2), fp32 multiply, one red.global.add.v4.f32.
// ---------------------------------------------------------------------------
__global__ void __launch_bounds__(256) scatter_kernel(
    const int*   __restrict__ r1, const int* __restrict__ c1, const float* __restrict__ v1,
    const int*   __restrict__ r2, const int* __restrict__ c2, const float* __restrict__ v2,
    float* __restrict__ out)
{
    int w    = (blockIdx.x * blockDim.x + threadIdx.x) >> 5;
    int lane = threadIdx.x & 31;
    if (w >= 2 * E_EDGES) return;

    int rel, e;
    const int *rr, *cc;
    const float* vv;
    if (w < E_EDGES) { rel = 0; e = w;           rr = r1; cc = c1; vv = v1; }
    else             { rel = 1; e = w - E_EDGES; rr = r2; cc = c2; vv = v2; }

    const int   row = __ldg(rr + e);
    const int   col = __ldg(cc + e);
    const float val = __ldg(vv + e);

    // g_x2 as float2 view: [n][64] float2; lane l -> float2 index rel*32 + l
    const float2* X = (const float2*)g_x2;
    float2 p = __ldg(X + (size_t)col * 64 + rel * 32 + lane);
    __half2 h0 = *(__half2*)&p.x;
    __half2 h1 = *(__half2*)&p.y;
    float2 f0 = __half22float2(h0);
    float2 f1 = __half22float2(h1);

    float* dst = out + (size_t)row * ODIM + lane * 4;
    asm volatile("red.global.add.v4.f32 [%0], {%1, %2, %3, %4};"
                 :: "l"(dst), "f"(f0.x * val), "f"(f0.y * val),
                    "f"(f1.x * val), "f"(f1.y * val)
                 : "memory");
}

// ---------------------------------------------------------------------------
// Zero-init and in-place ReLU (float4 grid-stride).
// ---------------------------------------------------------------------------
#define OUT_F4 ((size_t)N_NODES * ODIM / 4)   // 1,600,000

__global__ void zero_kernel(float4* __restrict__ out) {
    size_t i = (size_t)blockIdx.x * blockDim.x + threadIdx.x;
    if (i < OUT_F4) out[i] = make_float4(0.f, 0.f, 0.f, 0.f);
}

__global__ void relu_kernel(float4* __restrict__ out) {
    size_t i = (size_t)blockIdx.x * blockDim.x + threadIdx.x;
    if (i < OUT_F4) {
        float4 v = out[i];
        v.x = fmaxf(v.x, 0.f);
        v.y = fmaxf(v.y, 0.f);
        v.z = fmaxf(v.z, 0.f);
        v.w = fmaxf(v.w, 0.f);
        out[i] = v;
    }
}

// ---------------------------------------------------------------------------
extern "C" void kernel_launch(void* const* d_in, const int* in_sizes, int n_in,
                              void* d_out, int out_size)
{
    const float* inputs = (const float*)d_in[0];
    const int*   r1     = (const int*)  d_in[1];
    const int*   c1     = (const int*)  d_in[2];
    const float* v1     = (const float*)d_in[3];
    const int*   r2     = (const int*)  d_in[4];
    const int*   c2     = (const int*)  d_in[5];
    const float* v2     = (const float*)d_in[6];
    const float* W1     = (const float*)d_in[7];
    const float* W2     = (const float*)d_in[8];
    float*       out    = (float*)d_out;

    cudaFuncSetAttribute(gemm_tc_kernel,
                         cudaFuncAttributeMaxDynamicSharedMemorySize,
                         GEMM_SMEM_BYTES);

    // 1) zero the accumulator (d_out is poisoned by the harness)
    zero_kernel<<<(int)((OUT_F4 + 255) / 256), 256>>>((float4*)out);

    // 2) dense projection (tf32 x3 tensor cores), both relations
    {
        dim3 grid((N_NODES + 127) / 128, 2);
        gemm_tc_kernel<<<grid, 256, GEMM_SMEM_BYTES>>>(inputs, W1, W2);
    }

    // 3) edge scatter with fp16 feature reads + fp32 vector reductions
    {
        long total_warps = 2L * E_EDGES;
        int blocks = (int)((total_warps * 32 + 255) / 256);
        scatter_kernel<<<blocks, 256>>>(r1, c1, v1, r2, c2, v2, out);
    }

    // 4) ReLU in place
    relu_kernel<<<(int)((OUT_F4 + 255) / 256), 256>>>((float4*)out);
}

// round 4
// speedup vs baseline: 2.0844x; 1.7109x over previous
#include <cuda_runtime.h>
#include <cuda_fp16.h>
#include <cstdint>

#define N_NODES 50000
#define E_EDGES 800000
#define ODIM 128
#define M_CNT (2 * N_NODES)            // 100000 (rel,row) buckets
#define SCAN_B 1024
#define NBLK_SCAN ((M_CNT + SCAN_B - 1) / SCAN_B)   // 98

// Projected features fp16: [n][128] half2  (rel0 = half2 cols 0..63, rel1 = 64..127)
__device__ __half2 g_x2[(size_t)N_NODES * 128];
// Row-sorted edges: (col bits, val)
__device__ float2  g_edges[(size_t)2 * E_EDGES];
__device__ int     g_counts[M_CNT];
__device__ int     g_tmp[M_CNT];
__device__ int     g_bsum[NBLK_SCAN];
__device__ int     g_start[M_CNT + 1];
__device__ int     g_cursor[M_CNT];

// ---------------------------------------------------------------------------
// Tensor-core GEMM (tf32 x3 split) — unchanged from R3.
// ---------------------------------------------------------------------------
#define STRIDE 132
#define GEMM_SMEM_BYTES (2 * 128 * STRIDE * 4)   // 132 KB

__device__ __forceinline__ void cvt_split(float v, uint32_t& hi, uint32_t& lo) {
    asm("cvt.rna.tf32.f32 %0, %1;" : "=r"(hi) : "f"(v));
    float r = v - __uint_as_float(hi);
    asm("cvt.rna.tf32.f32 %0, %1;" : "=r"(lo) : "f"(r));
}

__device__ __forceinline__ void mma8(float* c, const uint32_t* a,
                                     uint32_t b0, uint32_t b1) {
    asm volatile(
        "mma.sync.aligned.m16n8k8.row.col.f32.tf32.tf32.f32 "
        "{%0,%1,%2,%3}, {%4,%5,%6,%7}, {%8,%9}, {%0,%1,%2,%3};"
        : "+f"(c[0]), "+f"(c[1]), "+f"(c[2]), "+f"(c[3])
        : "r"(a[0]), "r"(a[1]), "r"(a[2]), "r"(a[3]), "r"(b0), "r"(b1));
}

__global__ void __launch_bounds__(256) gemm_tc_kernel(
    const float* __restrict__ A,
    const float* __restrict__ W1,
    const float* __restrict__ W2)
{
    extern __shared__ float smem[];
    float* As = smem;                    // [m][k] stride 132
    float* Bs = smem + 128 * STRIDE;     // [n][k] stride 132

    const float* W = (blockIdx.y == 0) ? W1 : W2;
    const int row0 = blockIdx.x * 128;
    const int tid  = threadIdx.x;

    const float4* A4 = (const float4*)A;
    #pragma unroll
    for (int i = 0; i < 16; i++) {
        int idx = tid + i * 256;
        int m   = idx >> 5;
        int c4  = idx & 31;
        float4 v = make_float4(0.f, 0.f, 0.f, 0.f);
        if (row0 + m < N_NODES) v = A4[(size_t)(row0 + m) * 32 + c4];
        float* dst = As + m * STRIDE + c4 * 4;
        dst[0] = v.x; dst[1] = v.y; dst[2] = v.z; dst[3] = v.w;
    }
    const float4* W4 = (const float4*)W;
    #pragma unroll
    for (int i = 0; i < 16; i++) {
        int idx = tid + i * 256;
        int k   = idx >> 5;
        int n4  = idx & 31;
        float4 v = W4[idx];
        Bs[(n4 * 4 + 0) * STRIDE + k] = v.x;
        Bs[(n4 * 4 + 1) * STRIDE + k] = v.y;
        Bs[(n4 * 4 + 2) * STRIDE + k] = v.z;
        Bs[(n4 * 4 + 3) * STRIDE + k] = v.w;
    }
    __syncthreads();

    const int wid  = tid >> 5;
    const int lane = tid & 31;
    const int wm   = wid & 3;
    const int wn   = wid >> 2;
    const int g    = lane >> 2;
    const int t    = lane & 3;

    float c[2][8][4];
    #pragma unroll
    for (int mt = 0; mt < 2; mt++)
        #pragma unroll
        for (int nt = 0; nt < 8; nt++)
            #pragma unroll
            for (int j = 0; j < 4; j++) c[mt][nt][j] = 0.f;

    #pragma unroll 1
    for (int ks = 0; ks < 16; ks++) {
        const int k0 = ks * 8;
        uint32_t ah[2][4], al[2][4];
        #pragma unroll
        for (int mt = 0; mt < 2; mt++) {
            const int r0 = wm * 32 + mt * 16;
            float v0 = As[(r0 + g)     * STRIDE + k0 + t];
            float v1 = As[(r0 + g + 8) * STRIDE + k0 + t];
            float v2 = As[(r0 + g)     * STRIDE + k0 + t + 4];
            float v3 = As[(r0 + g + 8) * STRIDE + k0 + t + 4];
            cvt_split(v0, ah[mt][0], al[mt][0]);
            cvt_split(v1, ah[mt][1], al[mt][1]);
            cvt_split(v2, ah[mt][2], al[mt][2]);
            cvt_split(v3, ah[mt][3], al[mt][3]);
        }
        #pragma unroll
        for (int nt = 0; nt < 8; nt++) {
            const int n = wn * 64 + nt * 8 + g;
            float w0 = Bs[n * STRIDE + k0 + t];
            float w1 = Bs[n * STRIDE + k0 + t + 4];
            uint32_t bh0, bl0, bh1, bl1;
            cvt_split(w0, bh0, bl0);
            cvt_split(w1, bh1, bl1);
            #pragma unroll
            for (int mt = 0; mt < 2; mt++) {
                mma8(c[mt][nt], ah[mt], bh0, bh1);
                mma8(c[mt][nt], al[mt], bh0, bh1);
                mma8(c[mt][nt], ah[mt], bl0, bl1);
            }
        }
    }

    #pragma unroll
    for (int mt = 0; mt < 2; mt++) {
        #pragma unroll
        for (int nt = 0; nt < 8; nt++) {
            const int row_a = row0 + wm * 32 + mt * 16 + g;
            const int row_b = row_a + 8;
            const int h2col = blockIdx.y * 64 + wn * 32 + nt * 4 + t;
            if (row_a < N_NODES)
                g_x2[(size_t)row_a * 128 + h2col] =
                    __floats2half2_rn(c[mt][nt][0], c[mt][nt][1]);
            if (row_b < N_NODES)
                g_x2[(size_t)row_b * 128 + h2col] =
                    __floats2half2_rn(c[mt][nt][2], c[mt][nt][3]);
        }
    }
}

// ---------------------------------------------------------------------------
// Counting sort chain
// ---------------------------------------------------------------------------
__global__ void hist_kernel(const int* __restrict__ r1, const int* __restrict__ r2) {
    int t = blockIdx.x * blockDim.x + threadIdx.x;
    if (t >= 2 * E_EDGES) return;
    int rel = (t >= E_EDGES);
    int e   = t - rel * E_EDGES;
    int row = rel ? __ldg(r2 + e) : __ldg(r1 + e);
    atomicAdd(&g_counts[rel * N_NODES + row], 1);
}

// Pass 1: per-block exclusive scan (1024 threads), block sums to g_bsum.
__global__ void __launch_bounds__(SCAN_B) scan1_kernel() {
    __shared__ int s[SCAN_B];
    int i = blockIdx.x * SCAN_B + threadIdx.x;
    int v = (i < M_CNT) ? g_counts[i] : 0;
    s[threadIdx.x] = v;
    __syncthreads();
    for (int off = 1; off < SCAN_B; off <<= 1) {
        int u = 0;
        if ((int)threadIdx.x >= off) u = s[threadIdx.x - off];
        __syncthreads();
        if ((int)threadIdx.x >= off) s[threadIdx.x] += u;
        __syncthreads();
    }
    if (i < M_CNT) g_tmp[i] = s[threadIdx.x] - v;   // exclusive
    if (threadIdx.x == SCAN_B - 1) g_bsum[blockIdx.x] = s[SCAN_B - 1];
}

// Pass 2: one block scans the 98 block sums (exclusive, in place).
__global__ void __launch_bounds__(128) scan2_kernel() {
    __shared__ int s[128];
    int t = threadIdx.x;
    int v = (t < NBLK_SCAN) ? g_bsum[t] : 0;
    s[t] = v;
    __syncthreads();
    for (int off = 1; off < 128; off <<= 1) {
        int u = 0;
        if (t >= off) u = s[t - off];
        __syncthreads();
        if (t >= off) s[t] += u;
        __syncthreads();
    }
    if (t < NBLK_SCAN) g_bsum[t] = s[t] - v;        // exclusive
}

// Pass 3: add block offsets, emit g_start and g_cursor.
__global__ void __launch_bounds__(SCAN_B) scan3_kernel() {
    int i = blockIdx.x * SCAN_B + threadIdx.x;
    if (i < M_CNT) {
        int v = g_tmp[i] + g_bsum[blockIdx.x];
        g_start[i]  = v;
        g_cursor[i] = v;
    }
    if (i == 0) g_start[M_CNT] = 2 * E_EDGES;
}

__global__ void reorder_kernel(
    const int* __restrict__ r1, const int* __restrict__ c1, const float* __restrict__ v1,
    const int* __restrict__ r2, const int* __restrict__ c2, const float* __restrict__ v2)
{
    int t = blockIdx.x * blockDim.x + threadIdx.x;
    if (t >= 2 * E_EDGES) return;
    int rel = (t >= E_EDGES);
    int e   = t - rel * E_EDGES;
    int row, col; float val;
    if (rel == 0) { row = __ldg(r1 + e); col = __ldg(c1 + e); val = __ldg(v1 + e); }
    else          { row = __ldg(r2 + e); col = __ldg(c2 + e); val = __ldg(v2 + e); }
    int pos = atomicAdd(&g_cursor[rel * N_NODES + row], 1);
    g_edges[pos] = make_float2(__int_as_float(col), val);
}

// ---------------------------------------------------------------------------
// Gather: ONE WARP PER ROW, both relations; fp16 feature reads (8B/lane),
// fp32 accumulation, fused ReLU, single non-atomic float4 store per lane.
// ---------------------------------------------------------------------------
__global__ void __launch_bounds__(256) gather_kernel(float* __restrict__ out)
{
    const int w    = (blockIdx.x * blockDim.x + threadIdx.x) >> 5;
    const int lane = threadIdx.x & 31;
    if (w >= N_NODES) return;

    float4 acc = make_float4(0.f, 0.f, 0.f, 0.f);
    const float2* X = (const float2*)g_x2;   // [n][64] float2 (= 2 half2 each)

    #pragma unroll
    for (int rel = 0; rel < 2; rel++) {
        const int i  = rel * N_NODES + w;
        const int s  = g_start[i];
        const int en = g_start[i + 1];
        int e = s;
        // 2-wide software pipeline for MLP
        for (; e + 2 <= en; e += 2) {
            float2 p0 = __ldg(&g_edges[e]);
            float2 p1 = __ldg(&g_edges[e + 1]);
            int   col0 = __float_as_int(p0.x);
            int   col1 = __float_as_int(p1.x);
            float2 q0 = __ldg(X + (size_t)col0 * 64 + rel * 32 + lane);
            float2 q1 = __ldg(X + (size_t)col1 * 64 + rel * 32 + lane);
            float2 a0 = __half22float2(*(__half2*)&q0.x);
            float2 b0 = __half22float2(*(__half2*)&q0.y);
            float2 a1 = __half22float2(*(__half2*)&q1.x);
            float2 b1 = __half22float2(*(__half2*)&q1.y);
            acc.x += p0.y * a0.x + p1.y * a1.x;
            acc.y += p0.y * a0.y + p1.y * a1.y;
            acc.z += p0.y * b0.x + p1.y * b1.x;
            acc.w += p0.y * b0.y + p1.y * b1.y;
        }
        if (e < en) {
            float2 p = __ldg(&g_edges[e]);
            int col = __float_as_int(p.x);
            float2 q = __ldg(X + (size_t)col * 64 + rel * 32 + lane);
            float2 a = __half22float2(*(__half2*)&q.x);
            float2 b = __half22float2(*(__half2*)&q.y);
            acc.x += p.y * a.x;
            acc.y += p.y * a.y;
            acc.z += p.y * b.x;
            acc.w += p.y * b.y;
        }
    }

    acc.x = fmaxf(acc.x, 0.f);
    acc.y = fmaxf(acc.y, 0.f);
    acc.z = fmaxf(acc.z, 0.f);
    acc.w = fmaxf(acc.w, 0.f);
    ((float4*)out)[(size_t)w * 32 + lane] = acc;
}

// ---------------------------------------------------------------------------
extern "C" void kernel_launch(void* const* d_in, const int* in_sizes, int n_in,
                              void* d_out, int out_size)
{
    const float* inputs = (const float*)d_in[0];
    const int*   r1     = (const int*)  d_in[1];
    const int*   c1     = (const int*)  d_in[2];
    const float* v1     = (const float*)d_in[3];
    const int*   r2     = (const int*)  d_in[4];
    const int*   c2     = (const int*)  d_in[5];
    const float* v2     = (const float*)d_in[6];
    const float* W1     = (const float*)d_in[7];
    const float* W2     = (const float*)d_in[8];
    float*       out    = (float*)d_out;

    cudaFuncSetAttribute(gemm_tc_kernel,
                         cudaFuncAttributeMaxDynamicSharedMemorySize,
                         GEMM_SMEM_BYTES);

    // Sort chain
    void* counts_ptr = nullptr;
    cudaGetSymbolAddress(&counts_ptr, g_counts);
    cudaMemsetAsync(counts_ptr, 0, M_CNT * sizeof(int));
    hist_kernel<<<(2 * E_EDGES + 255) / 256, 256>>>(r1, r2);
    scan1_kernel<<<NBLK_SCAN, SCAN_B>>>();
    scan2_kernel<<<1, 128>>>();
    scan3_kernel<<<NBLK_SCAN, SCAN_B>>>();
    reorder_kernel<<<(2 * E_EDGES + 255) / 256, 256>>>(r1, c1, v1, r2, c2, v2);

    // Dense projection (tf32 x3 tensor cores)
    {
        dim3 grid((N_NODES + 127) / 128, 2);
        gemm_tc_kernel<<<grid, 256, GEMM_SMEM_BYTES>>>(inputs, W1, W2);
    }

    // Warp-per-row gather + fused ReLU (no atomics, no zero/relu pass)
    {
        long warps = N_NODES;
        int blocks = (int)((warps * 32 + 255) / 256);
        gather_kernel<<<blocks, 256>>>(out);
    }
}

// round 5
// speedup vs baseline: 2.3257x; 1.1158x over previous
#include <cuda_runtime.h>
#include <cuda_fp16.h>
#include <cstdint>

#define N_NODES 50000
#define E_EDGES 800000
#define ODIM 128
#define M_CNT (2 * N_NODES)            // 100000 (rel,row) buckets
#define SCAN_B 1024
#define NBLK_SCAN ((M_CNT + SCAN_B - 1) / SCAN_B)   // 98

// Projected features fp16: [n][128] half2 (rel0 = half2 cols 0..63, rel1 = 64..127)
__device__ __half2 g_x2[(size_t)N_NODES * 128];
// Row-sorted edges: (col bits, val)
__device__ float2  g_edges[(size_t)2 * E_EDGES];
__device__ int     g_counts[M_CNT];
__device__ int     g_tmp[M_CNT];
__device__ int     g_bsum[NBLK_SCAN];
__device__ int     g_start[M_CNT + 1];
__device__ int     g_cursor[M_CNT];

// ---------------------------------------------------------------------------
// Tensor-core GEMM (tf32 x3 split) — unchanged from R3/R4.
// ---------------------------------------------------------------------------
#define STRIDE 132
#define GEMM_SMEM_BYTES (2 * 128 * STRIDE * 4)   // 132 KB

__device__ __forceinline__ void cvt_split(float v, uint32_t& hi, uint32_t& lo) {
    asm("cvt.rna.tf32.f32 %0, %1;" : "=r"(hi) : "f"(v));
    float r = v - __uint_as_float(hi);
    asm("cvt.rna.tf32.f32 %0, %1;" : "=r"(lo) : "f"(r));
}

__device__ __forceinline__ void mma8(float* c, const uint32_t* a,
                                     uint32_t b0, uint32_t b1) {
    asm volatile(
        "mma.sync.aligned.m16n8k8.row.col.f32.tf32.tf32.f32 "
        "{%0,%1,%2,%3}, {%4,%5,%6,%7}, {%8,%9}, {%0,%1,%2,%3};"
        : "+f"(c[0]), "+f"(c[1]), "+f"(c[2]), "+f"(c[3])
        : "r"(a[0]), "r"(a[1]), "r"(a[2]), "r"(a[3]), "r"(b0), "r"(b1));
}

__global__ void __launch_bounds__(256) gemm_tc_kernel(
    const float* __restrict__ A,
    const float* __restrict__ W1,
    const float* __restrict__ W2)
{
    extern __shared__ float smem[];
    float* As = smem;
    float* Bs = smem + 128 * STRIDE;

    const float* W = (blockIdx.y == 0) ? W1 : W2;
    const int row0 = blockIdx.x * 128;
    const int tid  = threadIdx.x;

    const float4* A4 = (const float4*)A;
    #pragma unroll
    for (int i = 0; i < 16; i++) {
        int idx = tid + i * 256;
        int m   = idx >> 5;
        int c4  = idx & 31;
        float4 v = make_float4(0.f, 0.f, 0.f, 0.f);
        if (row0 + m < N_NODES) v = A4[(size_t)(row0 + m) * 32 + c4];
        float* dst = As + m * STRIDE + c4 * 4;
        dst[0] = v.x; dst[1] = v.y; dst[2] = v.z; dst[3] = v.w;
    }
    const float4* W4 = (const float4*)W;
    #pragma unroll
    for (int i = 0; i < 16; i++) {
        int idx = tid + i * 256;
        int k   = idx >> 5;
        int n4  = idx & 31;
        float4 v = W4[idx];
        Bs[(n4 * 4 + 0) * STRIDE + k] = v.x;
        Bs[(n4 * 4 + 1) * STRIDE + k] = v.y;
        Bs[(n4 * 4 + 2) * STRIDE + k] = v.z;
        Bs[(n4 * 4 + 3) * STRIDE + k] = v.w;
    }
    __syncthreads();

    const int wid  = tid >> 5;
    const int lane = tid & 31;
    const int wm   = wid & 3;
    const int wn   = wid >> 2;
    const int g    = lane >> 2;
    const int t    = lane & 3;

    float c[2][8][4];
    #pragma unroll
    for (int mt = 0; mt < 2; mt++)
        #pragma unroll
        for (int nt = 0; nt < 8; nt++)
            #pragma unroll
            for (int j = 0; j < 4; j++) c[mt][nt][j] = 0.f;

    #pragma unroll 1
    for (int ks = 0; ks < 16; ks++) {
        const int k0 = ks * 8;
        uint32_t ah[2][4], al[2][4];
        #pragma unroll
        for (int mt = 0; mt < 2; mt++) {
            const int r0 = wm * 32 + mt * 16;
            float v0 = As[(r0 + g)     * STRIDE + k0 + t];
            float v1 = As[(r0 + g + 8) * STRIDE + k0 + t];
            float v2 = As[(r0 + g)     * STRIDE + k0 + t + 4];
            float v3 = As[(r0 + g + 8) * STRIDE + k0 + t + 4];
            cvt_split(v0, ah[mt][0], al[mt][0]);
            cvt_split(v1, ah[mt][1], al[mt][1]);
            cvt_split(v2, ah[mt][2], al[mt][2]);
            cvt_split(v3, ah[mt][3], al[mt][3]);
        }
        #pragma unroll
        for (int nt = 0; nt < 8; nt++) {
            const int n = wn * 64 + nt * 8 + g;
            float w0 = Bs[n * STRIDE + k0 + t];
            float w1 = Bs[n * STRIDE + k0 + t + 4];
            uint32_t bh0, bl0, bh1, bl1;
            cvt_split(w0, bh0, bl0);
            cvt_split(w1, bh1, bl1);
            #pragma unroll
            for (int mt = 0; mt < 2; mt++) {
                mma8(c[mt][nt], ah[mt], bh0, bh1);
                mma8(c[mt][nt], al[mt], bh0, bh1);
                mma8(c[mt][nt], ah[mt], bl0, bl1);
            }
        }
    }

    #pragma unroll
    for (int mt = 0; mt < 2; mt++) {
        #pragma unroll
        for (int nt = 0; nt < 8; nt++) {
            const int row_a = row0 + wm * 32 + mt * 16 + g;
            const int row_b = row_a + 8;
            const int h2col = blockIdx.y * 64 + wn * 32 + nt * 4 + t;
            if (row_a < N_NODES)
                g_x2[(size_t)row_a * 128 + h2col] =
                    __floats2half2_rn(c[mt][nt][0], c[mt][nt][1]);
            if (row_b < N_NODES)
                g_x2[(size_t)row_b * 128 + h2col] =
                    __floats2half2_rn(c[mt][nt][2], c[mt][nt][3]);
        }
    }
}

// ---------------------------------------------------------------------------
// Counting sort chain (hist + reorder vectorized 4-wide)
// ---------------------------------------------------------------------------
#define E4 (E_EDGES / 4)   // 200000, E divisible by 4

__global__ void hist_kernel(const int* __restrict__ r1, const int* __restrict__ r2) {
    int t = blockIdx.x * blockDim.x + threadIdx.x;
    if (t >= 2 * E4) return;
    int rel = (t >= E4);
    const int4* rr = (const int4*)(rel ? r2 : r1);
    int4 r = __ldg(rr + (t - rel * E4));
    int base = rel * N_NODES;
    atomicAdd(&g_counts[base + r.x], 1);
    atomicAdd(&g_counts[base + r.y], 1);
    atomicAdd(&g_counts[base + r.z], 1);
    atomicAdd(&g_counts[base + r.w], 1);
}

__global__ void __launch_bounds__(SCAN_B) scan1_kernel() {
    __shared__ int s[SCAN_B];
    int i = blockIdx.x * SCAN_B + threadIdx.x;
    int v = (i < M_CNT) ? g_counts[i] : 0;
    s[threadIdx.x] = v;
    __syncthreads();
    for (int off = 1; off < SCAN_B; off <<= 1) {
        int u = 0;
        if ((int)threadIdx.x >= off) u = s[threadIdx.x - off];
        __syncthreads();
        if ((int)threadIdx.x >= off) s[threadIdx.x] += u;
        __syncthreads();
    }
    if (i < M_CNT) g_tmp[i] = s[threadIdx.x] - v;
    if (threadIdx.x == SCAN_B - 1) g_bsum[blockIdx.x] = s[SCAN_B - 1];
}

__global__ void __launch_bounds__(128) scan2_kernel() {
    __shared__ int s[128];
    int t = threadIdx.x;
    int v = (t < NBLK_SCAN) ? g_bsum[t] : 0;
    s[t] = v;
    __syncthreads();
    for (int off = 1; off < 128; off <<= 1) {
        int u = 0;
        if (t >= off) u = s[t - off];
        __syncthreads();
        if (t >= off) s[t] += u;
        __syncthreads();
    }
    if (t < NBLK_SCAN) g_bsum[t] = s[t] - v;
}

__global__ void __launch_bounds__(SCAN_B) scan3_kernel() {
    int i = blockIdx.x * SCAN_B + threadIdx.x;
    if (i < M_CNT) {
        int v = g_tmp[i] + g_bsum[blockIdx.x];
        g_start[i]  = v;
        g_cursor[i] = v;
    }
    if (i == 0) g_start[M_CNT] = 2 * E_EDGES;
}

__global__ void reorder_kernel(
    const int* __restrict__ r1, const int* __restrict__ c1, const float* __restrict__ v1,
    const int* __restrict__ r2, const int* __restrict__ c2, const float* __restrict__ v2)
{
    int t = blockIdx.x * blockDim.x + threadIdx.x;
    if (t >= 2 * E4) return;
    int rel = (t >= E4);
    int i4  = t - rel * E4;
    const int4*   rr = (const int4*)  (rel ? r2 : r1);
    const int4*   cc = (const int4*)  (rel ? c2 : c1);
    const float4* vv = (const float4*)(rel ? v2 : v1);
    int4   r = __ldg(rr + i4);
    int4   c = __ldg(cc + i4);
    float4 v = __ldg(vv + i4);
    int base = rel * N_NODES;
    int p0 = atomicAdd(&g_cursor[base + r.x], 1);
    int p1 = atomicAdd(&g_cursor[base + r.y], 1);
    int p2 = atomicAdd(&g_cursor[base + r.z], 1);
    int p3 = atomicAdd(&g_cursor[base + r.w], 1);
    g_edges[p0] = make_float2(__int_as_float(c.x), v.x);
    g_edges[p1] = make_float2(__int_as_float(c.y), v.y);
    g_edges[p2] = make_float2(__int_as_float(c.z), v.z);
    g_edges[p3] = make_float2(__int_as_float(c.w), v.w);
}

// ---------------------------------------------------------------------------
// Gather: one warp per row, both relations, 4-wide software pipeline,
// fp16 feature reads, fp32 accumulation, fused ReLU, non-atomic store.
// ---------------------------------------------------------------------------
__device__ __forceinline__ void acc_edge(float4& acc, float2 p,
                                         const float2* X, int rel, int lane) {
    int col = __float_as_int(p.x);
    float2 q = __ldg(X + (size_t)col * 64 + rel * 32 + lane);
    float2 a = __half22float2(*(__half2*)&q.x);
    float2 b = __half22float2(*(__half2*)&q.y);
    acc.x += p.y * a.x;
    acc.y += p.y * a.y;
    acc.z += p.y * b.x;
    acc.w += p.y * b.y;
}

__global__ void __launch_bounds__(256) gather_kernel(float* __restrict__ out)
{
    const int w    = (blockIdx.x * blockDim.x + threadIdx.x) >> 5;
    const int lane = threadIdx.x & 31;
    if (w >= N_NODES) return;

    float4 acc = make_float4(0.f, 0.f, 0.f, 0.f);
    const float2* X = (const float2*)g_x2;

    #pragma unroll
    for (int rel = 0; rel < 2; rel++) {
        const int i  = rel * N_NODES + w;
        const int s  = g_start[i];
        const int en = g_start[i + 1];
        int e = s;
        for (; e + 4 <= en; e += 4) {
            float2 p0 = __ldg(&g_edges[e]);
            float2 p1 = __ldg(&g_edges[e + 1]);
            float2 p2 = __ldg(&g_edges[e + 2]);
            float2 p3 = __ldg(&g_edges[e + 3]);
            acc_edge(acc, p0, X, rel, lane);
            acc_edge(acc, p1, X, rel, lane);
            acc_edge(acc, p2, X, rel, lane);
            acc_edge(acc, p3, X, rel, lane);
        }
        for (; e < en; e++) {
            float2 p = __ldg(&g_edges[e]);
            acc_edge(acc, p, X, rel, lane);
        }
    }

    acc.x = fmaxf(acc.x, 0.f);
    acc.y = fmaxf(acc.y, 0.f);
    acc.z = fmaxf(acc.z, 0.f);
    acc.w = fmaxf(acc.w, 0.f);
    ((float4*)out)[(size_t)w * 32 + lane] = acc;
}

// ---------------------------------------------------------------------------
extern "C" void kernel_launch(void* const* d_in, const int* in_sizes, int n_in,
                              void* d_out, int out_size)
{
    const float* inputs = (const float*)d_in[0];
    const int*   r1     = (const int*)  d_in[1];
    const int*   c1     = (const int*)  d_in[2];
    const float* v1     = (const float*)d_in[3];
    const int*   r2     = (const int*)  d_in[4];
    const int*   c2     = (const int*)  d_in[5];
    const float* v2     = (const float*)d_in[6];
    const float* W1     = (const float*)d_in[7];
    const float* W2     = (const float*)d_in[8];
    float*       out    = (float*)d_out;

    // One-time side stream + events (host-side resources; no device alloc).
    static cudaStream_t s_gemm = nullptr;
    static cudaEvent_t  e_fork = nullptr;
    static cudaEvent_t  e_join = nullptr;
    if (s_gemm == nullptr) {
        cudaStreamCreateWithFlags(&s_gemm, cudaStreamNonBlocking);
        cudaEventCreateWithFlags(&e_fork, cudaEventDisableTiming);
        cudaEventCreateWithFlags(&e_join, cudaEventDisableTiming);
        cudaFuncSetAttribute(gemm_tc_kernel,
                             cudaFuncAttributeMaxDynamicSharedMemorySize,
                             GEMM_SMEM_BYTES);
    }

    // Fork: GEMM runs on side stream, concurrent with the sort chain.
    cudaEventRecord(e_fork, 0);
    cudaStreamWaitEvent(s_gemm, e_fork, 0);
    {
        dim3 grid((N_NODES + 127) / 128, 2);
        gemm_tc_kernel<<<grid, 256, GEMM_SMEM_BYTES, s_gemm>>>(inputs, W1, W2);
    }
    cudaEventRecord(e_join, s_gemm);

    // Sort chain on the capture (default) stream.
    void* counts_ptr = nullptr;
    cudaGetSymbolAddress(&counts_ptr, g_counts);
    cudaMemsetAsync(counts_ptr, 0, M_CNT * sizeof(int));
    hist_kernel<<<(2 * E4 + 255) / 256, 256>>>(r1, r2);
    scan1_kernel<<<NBLK_SCAN, SCAN_B>>>();
    scan2_kernel<<<1, 128>>>();
    scan3_kernel<<<NBLK_SCAN, SCAN_B>>>();
    reorder_kernel<<<(2 * E4 + 255) / 256, 256>>>(r1, c1, v1, r2, c2, v2);

    // Join, then gather + fused ReLU.
    cudaStreamWaitEvent(0, e_join, 0);
    {
        long warps = N_NODES;
        int blocks = (int)((warps * 32 + 255) / 256);
        gather_kernel<<<blocks, 256>>>(out);
    }
}

// round 6
// speedup vs baseline: 2.3512x; 1.0109x over previous
#include <cuda_runtime.h>
#include <cuda_fp16.h>
#include <cstdint>

#define N_NODES 50000
#define E_EDGES 800000
#define ODIM 128
#define M_CNT (2 * N_NODES)            // 100000 (rel,row) buckets
#define SCAN_B 1024
#define NBLK_SCAN ((M_CNT + SCAN_B - 1) / SCAN_B)   // 98

// Projected features fp16: [n][128] half2 (rel0 = half2 cols 0..63, rel1 = 64..127)
__device__ __half2 g_x2[(size_t)N_NODES * 128];
// Row-sorted edges: (col bits, val)
__device__ float2  g_edges[(size_t)2 * E_EDGES];
__device__ int     g_counts[M_CNT];
__device__ int     g_tmp[M_CNT];
__device__ int     g_bsum[NBLK_SCAN];
__device__ int     g_start[M_CNT + 1];
__device__ int     g_cursor[M_CNT];

// ---------------------------------------------------------------------------
// Tensor-core GEMM (tf32 x3 split) — unchanged.
// ---------------------------------------------------------------------------
#define STRIDE 132
#define GEMM_SMEM_BYTES (2 * 128 * STRIDE * 4)   // 132 KB

__device__ __forceinline__ void cvt_split(float v, uint32_t& hi, uint32_t& lo) {
    asm("cvt.rna.tf32.f32 %0, %1;" : "=r"(hi) : "f"(v));
    float r = v - __uint_as_float(hi);
    asm("cvt.rna.tf32.f32 %0, %1;" : "=r"(lo) : "f"(r));
}

__device__ __forceinline__ void mma8(float* c, const uint32_t* a,
                                     uint32_t b0, uint32_t b1) {
    asm volatile(
        "mma.sync.aligned.m16n8k8.row.col.f32.tf32.tf32.f32 "
        "{%0,%1,%2,%3}, {%4,%5,%6,%7}, {%8,%9}, {%0,%1,%2,%3};"
        : "+f"(c[0]), "+f"(c[1]), "+f"(c[2]), "+f"(c[3])
        : "r"(a[0]), "r"(a[1]), "r"(a[2]), "r"(a[3]), "r"(b0), "r"(b1));
}

__global__ void __launch_bounds__(256) gemm_tc_kernel(
    const float* __restrict__ A,
    const float* __restrict__ W1,
    const float* __restrict__ W2)
{
    extern __shared__ float smem[];
    float* As = smem;
    float* Bs = smem + 128 * STRIDE;

    const float* W = (blockIdx.y == 0) ? W1 : W2;
    const int row0 = blockIdx.x * 128;
    const int tid  = threadIdx.x;

    const float4* A4 = (const float4*)A;
    #pragma unroll
    for (int i = 0; i < 16; i++) {
        int idx = tid + i * 256;
        int m   = idx >> 5;
        int c4  = idx & 31;
        float4 v = make_float4(0.f, 0.f, 0.f, 0.f);
        if (row0 + m < N_NODES) v = A4[(size_t)(row0 + m) * 32 + c4];
        float* dst = As + m * STRIDE + c4 * 4;
        dst[0] = v.x; dst[1] = v.y; dst[2] = v.z; dst[3] = v.w;
    }
    const float4* W4 = (const float4*)W;
    #pragma unroll
    for (int i = 0; i < 16; i++) {
        int idx = tid + i * 256;
        int k   = idx >> 5;
        int n4  = idx & 31;
        float4 v = W4[idx];
        Bs[(n4 * 4 + 0) * STRIDE + k] = v.x;
        Bs[(n4 * 4 + 1) * STRIDE + k] = v.y;
        Bs[(n4 * 4 + 2) * STRIDE + k] = v.z;
        Bs[(n4 * 4 + 3) * STRIDE + k] = v.w;
    }
    __syncthreads();

    const int wid  = tid >> 5;
    const int lane = tid & 31;
    const int wm   = wid & 3;
    const int wn   = wid >> 2;
    const int g    = lane >> 2;
    const int t    = lane & 3;

    float c[2][8][4];
    #pragma unroll
    for (int mt = 0; mt < 2; mt++)
        #pragma unroll
        for (int nt = 0; nt < 8; nt++)
            #pragma unroll
            for (int j = 0; j < 4; j++) c[mt][nt][j] = 0.f;

    #pragma unroll 1
    for (int ks = 0; ks < 16; ks++) {
        const int k0 = ks * 8;
        uint32_t ah[2][4], al[2][4];
        #pragma unroll
        for (int mt = 0; mt < 2; mt++) {
            const int r0 = wm * 32 + mt * 16;
            float v0 = As[(r0 + g)     * STRIDE + k0 + t];
            float v1 = As[(r0 + g + 8) * STRIDE + k0 + t];
            float v2 = As[(r0 + g)     * STRIDE + k0 + t + 4];
            float v3 = As[(r0 + g + 8) * STRIDE + k0 + t + 4];
            cvt_split(v0, ah[mt][0], al[mt][0]);
            cvt_split(v1, ah[mt][1], al[mt][1]);
            cvt_split(v2, ah[mt][2], al[mt][2]);
            cvt_split(v3, ah[mt][3], al[mt][3]);
        }
        #pragma unroll
        for (int nt = 0; nt < 8; nt++) {
            const int n = wn * 64 + nt * 8 + g;
            float w0 = Bs[n * STRIDE + k0 + t];
            float w1 = Bs[n * STRIDE + k0 + t + 4];
            uint32_t bh0, bl0, bh1, bl1;
            cvt_split(w0, bh0, bl0);
            cvt_split(w1, bh1, bl1);
            #pragma unroll
            for (int mt = 0; mt < 2; mt++) {
                mma8(c[mt][nt], ah[mt], bh0, bh1);
                mma8(c[mt][nt], al[mt], bh0, bh1);
                mma8(c[mt][nt], ah[mt], bl0, bl1);
            }
        }
    }

    #pragma unroll
    for (int mt = 0; mt < 2; mt++) {
        #pragma unroll
        for (int nt = 0; nt < 8; nt++) {
            const int row_a = row0 + wm * 32 + mt * 16 + g;
            const int row_b = row_a + 8;
            const int h2col = blockIdx.y * 64 + wn * 32 + nt * 4 + t;
            if (row_a < N_NODES)
                g_x2[(size_t)row_a * 128 + h2col] =
                    __floats2half2_rn(c[mt][nt][0], c[mt][nt][1]);
            if (row_b < N_NODES)
                g_x2[(size_t)row_b * 128 + h2col] =
                    __floats2half2_rn(c[mt][nt][2], c[mt][nt][3]);
        }
    }
}

// ---------------------------------------------------------------------------
// Counting sort chain
// ---------------------------------------------------------------------------
#define E4 (E_EDGES / 4)   // 200000

__global__ void hist_kernel(const int* __restrict__ r1, const int* __restrict__ r2) {
    int t = blockIdx.x * blockDim.x + threadIdx.x;
    if (t >= 2 * E4) return;
    int rel = (t >= E4);
    const int4* rr = (const int4*)(rel ? r2 : r1);
    int4 r = __ldg(rr + (t - rel * E4));
    int base = rel * N_NODES;
    atomicAdd(&g_counts[base + r.x], 1);
    atomicAdd(&g_counts[base + r.y], 1);
    atomicAdd(&g_counts[base + r.z], 1);
    atomicAdd(&g_counts[base + r.w], 1);
}

__global__ void __launch_bounds__(SCAN_B) scan1_kernel() {
    __shared__ int s[SCAN_B];
    int i = blockIdx.x * SCAN_B + threadIdx.x;
    int v = (i < M_CNT) ? g_counts[i] : 0;
    s[threadIdx.x] = v;
    __syncthreads();
    for (int off = 1; off < SCAN_B; off <<= 1) {
        int u = 0;
        if ((int)threadIdx.x >= off) u = s[threadIdx.x - off];
        __syncthreads();
        if ((int)threadIdx.x >= off) s[threadIdx.x] += u;
        __syncthreads();
    }
    if (i < M_CNT) g_tmp[i] = s[threadIdx.x] - v;
    if (threadIdx.x == SCAN_B - 1) g_bsum[blockIdx.x] = s[SCAN_B - 1];
}

// scan3 with inlined block-offset computation (scan2 eliminated):
// first warp sums g_bsum[0..blockIdx.x), then all threads add it.
__global__ void __launch_bounds__(SCAN_B) scan3_kernel() {
    __shared__ int s_off;
    int t = threadIdx.x;
    if (t < 32) {
        int p = 0;
        for (int j = t; j < (int)blockIdx.x; j += 32) p += g_bsum[j];
        #pragma unroll
        for (int o = 16; o > 0; o >>= 1)
            p += __shfl_down_sync(0xffffffff, p, o);
        if (t == 0) s_off = p;
    }
    __syncthreads();
    int i = blockIdx.x * SCAN_B + t;
    if (i < M_CNT) {
        int v = g_tmp[i] + s_off;
        g_start[i]  = v;
        g_cursor[i] = v;
    }
    if (i == 0) g_start[M_CNT] = 2 * E_EDGES;
}

__global__ void reorder_kernel(
    const int* __restrict__ r1, const int* __restrict__ c1, const float* __restrict__ v1,
    const int* __restrict__ r2, const int* __restrict__ c2, const float* __restrict__ v2)
{
    int t = blockIdx.x * blockDim.x + threadIdx.x;
    if (t >= 2 * E4) return;
    int rel = (t >= E4);
    int i4  = t - rel * E4;
    const int4*   rr = (const int4*)  (rel ? r2 : r1);
    const int4*   cc = (const int4*)  (rel ? c2 : c1);
    const float4* vv = (const float4*)(rel ? v2 : v1);
    int4   r = __ldg(rr + i4);
    int4   c = __ldg(cc + i4);
    float4 v = __ldg(vv + i4);
    int base = rel * N_NODES;
    int p0 = atomicAdd(&g_cursor[base + r.x], 1);
    int p1 = atomicAdd(&g_cursor[base + r.y], 1);
    int p2 = atomicAdd(&g_cursor[base + r.z], 1);
    int p3 = atomicAdd(&g_cursor[base + r.w], 1);
    g_edges[p0] = make_float2(__int_as_float(c.x), v.x);
    g_edges[p1] = make_float2(__int_as_float(c.y), v.y);
    g_edges[p2] = make_float2(__int_as_float(c.z), v.z);
    g_edges[p3] = make_float2(__int_as_float(c.w), v.w);
}

// ---------------------------------------------------------------------------
// Gather: one warp per row; each 16-lane HALF-WARP handles one edge with
// 128-bit feature loads (16 x float4 = 256 B = full relation row).
// Both relations accumulate into the same 8 fp32 regs (output = relu(y1+y2)).
// Cross-half shfl reduction + fused ReLU + one ST.128 per lane.
// ---------------------------------------------------------------------------
__device__ __forceinline__ void acc_edge16(float* a, float2 p,
                                           const float4* X4, int rel, int hl) {
    int col = __float_as_int(p.x);
    float4 q = __ldg(X4 + (size_t)col * 32 + rel * 16 + hl);
    float2 f0 = __half22float2(*(__half2*)&q.x);
    float2 f1 = __half22float2(*(__half2*)&q.y);
    float2 f2 = __half22float2(*(__half2*)&q.z);
    float2 f3 = __half22float2(*(__half2*)&q.w);
    a[0] += p.y * f0.x;  a[1] += p.y * f0.y;
    a[2] += p.y * f1.x;  a[3] += p.y * f1.y;
    a[4] += p.y * f2.x;  a[5] += p.y * f2.y;
    a[6] += p.y * f3.x;  a[7] += p.y * f3.y;
}

__global__ void __launch_bounds__(256) gather_kernel(float* __restrict__ out)
{
    const int w    = (blockIdx.x * blockDim.x + threadIdx.x) >> 5;
    const int lane = threadIdx.x & 31;
    if (w >= N_NODES) return;

    const int half = lane >> 4;     // 0 or 1
    const int hl   = lane & 15;     // lane within half-warp

    float a[8];
    #pragma unroll
    for (int j = 0; j < 8; j++) a[j] = 0.f;

    const float4* X4 = (const float4*)g_x2;   // [n][32] float4

    #pragma unroll
    for (int rel = 0; rel < 2; rel++) {
        const int i  = rel * N_NODES + w;
        const int s  = g_start[i];
        const int en = g_start[i + 1];
        // This half-warp covers edges s+half, s+half+2, ... (stride 2),
        // unrolled 2x (stride 4) for MLP.
        int e = s + half;
        for (; e + 2 < en; e += 4) {
            float2 p0 = __ldg(&g_edges[e]);
            float2 p1 = __ldg(&g_edges[e + 2]);
            acc_edge16(a, p0, X4, rel, hl);
            acc_edge16(a, p1, X4, rel, hl);
        }
        if (e < en) {
            float2 p = __ldg(&g_edges[e]);
            acc_edge16(a, p, X4, rel, hl);
        }
    }

    // Combine the two half-warps' partial sums.
    #pragma unroll
    for (int j = 0; j < 8; j++)
        a[j] += __shfl_xor_sync(0xffffffff, a[j], 16);

    // Write: lane (half, hl) stores float4 {a[half*4]..a[half*4+3]} at
    // row*32 + hl*2 + half. Full 512 B per row, fully coalesced.
    const int j0 = half * 4;
    float4 o;
    o.x = fmaxf(a[j0 + 0], 0.f);
    o.y = fmaxf(a[j0 + 1], 0.f);
    o.z = fmaxf(a[j0 + 2], 0.f);
    o.w = fmaxf(a[j0 + 3], 0.f);
    ((float4*)out)[(size_t)w * 32 + hl * 2 + half] = o;
}

// ---------------------------------------------------------------------------
extern "C" void kernel_launch(void* const* d_in, const int* in_sizes, int n_in,
                              void* d_out, int out_size)
{
    const float* inputs = (const float*)d_in[0];
    const int*   r1     = (const int*)  d_in[1];
    const int*   c1     = (const int*)  d_in[2];
    const float* v1     = (const float*)d_in[3];
    const int*   r2     = (const int*)  d_in[4];
    const int*   c2     = (const int*)  d_in[5];
    const float* v2     = (const float*)d_in[6];
    const float* W1     = (const float*)d_in[7];
    const float* W2     = (const float*)d_in[8];
    float*       out    = (float*)d_out;

    static cudaStream_t s_gemm = nullptr;
    static cudaEvent_t  e_fork = nullptr;
    static cudaEvent_t  e_join = nullptr;
    if (s_gemm == nullptr) {
        cudaStreamCreateWithFlags(&s_gemm, cudaStreamNonBlocking);
        cudaEventCreateWithFlags(&e_fork, cudaEventDisableTiming);
        cudaEventCreateWithFlags(&e_join, cudaEventDisableTiming);
        cudaFuncSetAttribute(gemm_tc_kernel,
                             cudaFuncAttributeMaxDynamicSharedMemorySize,
                             GEMM_SMEM_BYTES);
    }

    // Fork: GEMM on side stream, concurrent with the sort chain.
    cudaEventRecord(e_fork, 0);
    cudaStreamWaitEvent(s_gemm, e_fork, 0);
    {
        dim3 grid((N_NODES + 127) / 128, 2);
        gemm_tc_kernel<<<grid, 256, GEMM_SMEM_BYTES, s_gemm>>>(inputs, W1, W2);
    }
    cudaEventRecord(e_join, s_gemm);

    // Sort chain on the capture stream.
    void* counts_ptr = nullptr;
    cudaGetSymbolAddress(&counts_ptr, g_counts);
    cudaMemsetAsync(counts_ptr, 0, M_CNT * sizeof(int));
    hist_kernel<<<(2 * E4 + 255) / 256, 256>>>(r1, r2);
    scan1_kernel<<<NBLK_SCAN, SCAN_B>>>();
    scan3_kernel<<<NBLK_SCAN, SCAN_B>>>();
    reorder_kernel<<<(2 * E4 + 255) / 256, 256>>>(r1, c1, v1, r2, c2, v2);

    // Join, then gather + fused ReLU.
    cudaStreamWaitEvent(0, e_join, 0);
    {
        long warps = N_NODES;
        int blocks = (int)((warps * 32 + 255) / 256);
        gather_kernel<<<blocks, 256>>>(out);
    }
}